// round 13
// baseline (speedup 1.0000x reference)
#include <cuda_runtime.h>
#include <cuda_fp16.h>
#include <math.h>

// Problem constants (fixed by the dataset)
#define Bb   4
#define Ss   2048
#define Dd   512
#define Hh   8
#define DK   64
#define Rr   8
#define TR   16
#define NBH  (Bb*Hh)                // 32
#define NNODES (NBH*Ss)             // 65536
#define NEDGE  (NBH*TR*Ss)          // 1048576
#define MROWS (Bb*Ss)               // 8192

// ---------------- scratch (device globals; no allocation allowed) -------------
__device__ float g_q[NBH*Ss*DK];
__device__ float g_k[NBH*Ss*DK];
__device__ float g_v[NBH*Ss*DK];
__device__ __align__(16) __half g_kv[NBH*Ss*128];   // interleaved: halves 4p..4p+3 = k2p,k2p+1,v2p,v2p+1
__device__ int   g_cnt[NNODES];
__device__ int   g_off[NBH*(Ss+1)];
__device__ int   g_info[NEDGE];
__device__ __align__(16) __half g_ah[3*MROWS*Dd];   // fp16 inputs (q,k,v)
__device__ __align__(16) __half g_wh[4*Dd*Dd];      // weight hi
__device__ __align__(16) __half g_wl[4*Dd*Dd];      // weight lo
__device__ __align__(16) __half g_atth[MROWS*Dd];   // attn output fp16

// ======================= helpers =============================================
__device__ __forceinline__ unsigned su32(const void* p){
    unsigned a;
    asm("{ .reg .u64 t; cvta.to.shared.u64 t, %1; cvt.u32.u64 %0, t; }"
        : "=r"(a) : "l"(p));
    return a;
}
__device__ __forceinline__ void cpa16(unsigned dst, const void* src){
    asm volatile("cp.async.cg.shared.global [%0], [%1], 16;"
                 :: "r"(dst), "l"(src));
}
__device__ __forceinline__ void cpa_commit(){
    asm volatile("cp.async.commit_group;");
}
__device__ __forceinline__ void cpa_wait2(){
    asm volatile("cp.async.wait_group 2;");
}
__device__ __forceinline__ void ldmx4(unsigned* r, unsigned addr){
    asm volatile("ldmatrix.sync.aligned.m8n8.x4.shared.b16 {%0,%1,%2,%3}, [%4];"
                 : "=r"(r[0]), "=r"(r[1]), "=r"(r[2]), "=r"(r[3]) : "r"(addr));
}
__device__ __forceinline__ void mma_f16(float* d, const unsigned* a, const unsigned* b){
    asm volatile(
        "mma.sync.aligned.m16n8k16.row.col.f32.f16.f16.f32 "
        "{%0,%1,%2,%3}, {%4,%5,%6,%7}, {%8,%9}, {%0,%1,%2,%3};"
        : "+f"(d[0]), "+f"(d[1]), "+f"(d[2]), "+f"(d[3])
        : "r"(a[0]), "r"(a[1]), "r"(a[2]), "r"(a[3]), "r"(b[0]), "r"(b[1]));
}
// 64-byte rows, 16B-granule XOR swizzle: conflict-free ldmatrix
__device__ __forceinline__ unsigned swz(unsigned row, unsigned kb){
    return row * 64u + ((((kb >> 4) ^ ((row >> 1) & 3u)) << 4) | (kb & 15u));
}

// ---------------- conversion pre-passes --------------------------------------
__global__ __launch_bounds__(256) void conv_w(
    const float* __restrict__ Wq, const float* __restrict__ Wk,
    const float* __restrict__ Wv, const float* __restrict__ Wo)
{
    const int z = blockIdx.y;
    const float* W = (z == 0) ? Wq : (z == 1) ? Wk : (z == 2) ? Wv : Wo;
    const int i = blockIdx.x * 256 + threadIdx.x;
    float4 v = ((const float4*)W)[i];
    __half hx = __float2half(v.x), hy = __float2half(v.y);
    __half hz = __float2half(v.z), hw = __float2half(v.w);
    const size_t o = (size_t)z * (Dd*Dd) + (size_t)i * 4;
    *(__half2*)&g_wh[o]     = __halves2half2(hx, hy);
    *(__half2*)&g_wh[o + 2] = __halves2half2(hz, hw);
    *(__half2*)&g_wl[o]     = __halves2half2(__float2half(v.x - __half2float(hx)),
                                             __float2half(v.y - __half2float(hy)));
    *(__half2*)&g_wl[o + 2] = __halves2half2(__float2half(v.z - __half2float(hz)),
                                             __float2half(v.w - __half2float(hw)));
}

__global__ __launch_bounds__(256) void conv_in(
    const float* __restrict__ q, const float* __restrict__ k,
    const float* __restrict__ v)
{
    const int z = blockIdx.y;
    const float* X = (z == 0) ? q : (z == 1) ? k : v;
    const int i = blockIdx.x * 256 + threadIdx.x;
    if (z == 0 && i < NNODES) g_cnt[i] = 0;
    float4 val = ((const float4*)X)[i];
    const size_t o = (size_t)z * (MROWS*Dd) + (size_t)i * 4;
    *(__half2*)&g_ah[o]     = __floats2half2_rn(val.x, val.y);
    *(__half2*)&g_ah[o + 2] = __floats2half2_rn(val.z, val.w);
}

// repack g_k/g_v (fp32) -> interleaved fp16 g_kv, fully coalesced
__global__ __launch_bounds__(256) void conv_kv()
{
    const int t = blockIdx.x * 256 + threadIdx.x;   // NNODES*16 threads
    const int node = t >> 4, seg = t & 15;          // seg: 4 consecutive dims
    const size_t ib = (size_t)node * DK + seg * 4;
    float4 kf = *(const float4*)&g_k[ib];
    float4 vf = *(const float4*)&g_v[ib];
    uint4 o;
    __half2 t0 = __floats2half2_rn(kf.x, kf.y); o.x = *(unsigned*)&t0;
    __half2 t1 = __floats2half2_rn(vf.x, vf.y); o.y = *(unsigned*)&t1;
    __half2 t2 = __floats2half2_rn(kf.z, kf.w); o.z = *(unsigned*)&t2;
    __half2 t3 = __floats2half2_rn(vf.z, vf.w); o.w = *(unsigned*)&t3;
    *(uint4*)&g_kv[(size_t)node * 128 + seg * 8] = o;
}

// ======== fp16 tensor-core GEMM (R9 version, unchanged) ======================
#define STG_BH 8192
#define STG_BL 12288
#define STAGE  16384

__global__ __launch_bounds__(256, 2) void gemm_tc(
    const float* __restrict__ B0, const float* __restrict__ B1,
    const float* __restrict__ B2, float* __restrict__ C_ext, int mode)
{
    extern __shared__ char dsm[];
    const unsigned sb = su32(dsm);

    const int z = blockIdx.z;
    const __half* A;
    const __half* Wh;
    const __half* Wl;
    const float* bias;
    float* dst;
    if (mode == 0) {
        A = g_ah + (size_t)z * (MROWS*Dd);
        Wh = g_wh + (size_t)z * (Dd*Dd);
        Wl = g_wl + (size_t)z * (Dd*Dd);
        bias = (z == 0) ? B0 : (z == 1) ? B1 : B2;
        dst = (z == 0) ? g_q : (z == 1) ? g_k : g_v;
    } else {
        A = g_atth;
        Wh = g_wh + (size_t)3 * (Dd*Dd);
        Wl = g_wl + (size_t)3 * (Dd*Dd);
        bias = B0;
        dst = C_ext;
    }

    const int tid = threadIdx.x;
    const int wid = tid >> 5, lane = tid & 31;
    const int wm = wid & 3, wn = wid >> 2;
    const int m0 = blockIdx.y * 128, n0 = blockIdx.x * 64;

    const int arow = tid >> 1;
    const int ap0 = (2 * tid) & 3;
    const int brow = tid >> 2, bp = tid & 3;
    const __half* Asrc = A + (size_t)(m0 + arow) * Dd + ap0 * 8;
    const __half* Whsrc = Wh + (size_t)(n0 + brow) * Dd + bp * 8;
    const __half* Wlsrc = Wl + (size_t)(n0 + brow) * Dd + bp * 8;
    const unsigned dA0 = swz(arow, ap0 * 16);
    const unsigned dA1 = swz(arow, ap0 * 16 + 16);
    const unsigned dB  = swz(brow, bp * 16);

    float acc[2][4][4];
#pragma unroll
    for (int mt = 0; mt < 2; mt++)
#pragma unroll
        for (int nt = 0; nt < 4; nt++)
#pragma unroll
            for (int i = 0; i < 4; i++) acc[mt][nt][i] = 0.f;

#pragma unroll
    for (int c = 0; c < 3; c++) {
        const unsigned st = sb + c * STAGE;
        cpa16(st + dA0, Asrc + c * 32);
        cpa16(st + dA1, Asrc + c * 32 + 8);
        cpa16(st + STG_BH + dB, Whsrc + c * 32);
        cpa16(st + STG_BL + dB, Wlsrc + c * 32);
        cpa_commit();
    }

    for (int c = 0; c < 16; c++) {
        cpa_wait2();
        __syncthreads();
        if (c + 3 < 16) {
            const unsigned st = sb + ((c + 3) & 3) * STAGE;
            cpa16(st + dA0, Asrc + (c + 3) * 32);
            cpa16(st + dA1, Asrc + (c + 3) * 32 + 8);
            cpa16(st + STG_BH + dB, Whsrc + (c + 3) * 32);
            cpa16(st + STG_BL + dB, Wlsrc + (c + 3) * 32);
        }
        cpa_commit();

        const unsigned st = sb + (c & 3) * STAGE;
#pragma unroll
        for (int ks = 0; ks < 2; ks++) {
            const unsigned kb = ks * 32;
            unsigned ah[2][4], bh[4][2], bl[4][2];
#pragma unroll
            for (int mt = 0; mt < 2; mt++) {
                unsigned r = wm * 32 + mt * 16 + (lane & 15);
                unsigned kbyte = kb + (lane >> 4) * 16;
                ldmx4(ah[mt], st + swz(r, kbyte));
            }
#pragma unroll
            for (int p = 0; p < 2; p++) {
                unsigned r = wn * 32 + p * 16 + (lane & 7) + ((lane >> 4) << 3);
                unsigned kbyte = kb + ((lane >> 3) & 1) * 16;
                unsigned t[4];
                ldmx4(t, st + STG_BH + swz(r, kbyte));
                bh[2*p][0] = t[0]; bh[2*p][1] = t[1];
                bh[2*p+1][0] = t[2]; bh[2*p+1][1] = t[3];
                ldmx4(t, st + STG_BL + swz(r, kbyte));
                bl[2*p][0] = t[0]; bl[2*p][1] = t[1];
                bl[2*p+1][0] = t[2]; bl[2*p+1][1] = t[3];
            }
#pragma unroll
            for (int mt = 0; mt < 2; mt++)
#pragma unroll
                for (int nt = 0; nt < 4; nt++) {
                    mma_f16(acc[mt][nt], ah[mt], bh[nt]);
                    mma_f16(acc[mt][nt], ah[mt], bl[nt]);
                }
        }
        __syncthreads();
    }

#pragma unroll
    for (int nt = 0; nt < 4; nt++) {
        const int ncol = n0 + wn * 32 + nt * 8 + 2 * (lane & 3);
        const float b0 = bias[ncol], b1 = bias[ncol + 1];
#pragma unroll
        for (int mt = 0; mt < 2; mt++) {
            const int r0 = m0 + wm * 32 + mt * 16 + (lane >> 2);
            float2 v0 = make_float2(acc[mt][nt][0] + b0, acc[mt][nt][1] + b1);
            float2 v1 = make_float2(acc[mt][nt][2] + b0, acc[mt][nt][3] + b1);
            if (mode == 1) {
                *(float2*)(dst + (size_t)r0 * Dd + ncol) = v0;
                *(float2*)(dst + (size_t)(r0 + 8) * Dd + ncol) = v1;
            } else {
                const int h = ncol >> 6, d = ncol & 63;
                int b = r0 >> 11, s = r0 & (Ss - 1);
                *(float2*)(dst + (size_t)(((b * Hh + h) * Ss + s)) * DK + d) = v0;
                b = (r0 + 8) >> 11; s = (r0 + 8) & (Ss - 1);
                *(float2*)(dst + (size_t)(((b * Hh + h) * Ss + s)) * DK + d) = v1;
            }
        }
    }
}

// ---------------- per-edge counting (index-only, R9 scalar form) -------------
__global__ __launch_bounds__(256) void k_count(
    const int* __restrict__ snod, const int* __restrict__ enod)
{
    int t = blockIdx.x * 256 + threadIdx.x;       // 524288
    int jm = (t >> 11) & 7;
    int bh = t >> 14;
    int nidx = t;
    int sv = snod[nidx];
    if (sv < 0) return;
    int ev = enod[nidx] & (Ss - 1);
    int sv2 = sv & (Ss - 1);
    int base = bh * Ss;
    if (jm != 0) atomicAdd(&g_cnt[base + ev], 1);
    atomicAdd(&g_cnt[base + sv2], 1);
}

// ---------------- exclusive scan of per-node counts per (b,h) --------------
__global__ __launch_bounds__(256) void k_scan()
{
    __shared__ int partial[256];
    int bh = blockIdx.x;
    int t = threadIdx.x;
    int base = bh * Ss + t * 8;
    int c[8]; int sum = 0;
#pragma unroll
    for (int i = 0; i < 8; i++) { c[i] = g_cnt[base + i]; sum += c[i]; }
    partial[t] = sum;
    __syncthreads();
    for (int off = 1; off < 256; off <<= 1) {
        int v = (t >= off) ? partial[t - off] : 0;
        __syncthreads();
        partial[t] += v;
        __syncthreads();
    }
    int run = partial[t] - sum;
    int obase = bh * (Ss + 1) + t * 8;
#pragma unroll
    for (int i = 0; i < 8; i++) { g_off[obase + i] = run; run += c[i]; }
    if (t == 255) g_off[bh * (Ss + 1) + Ss] = run;
#pragma unroll
    for (int i = 0; i < 8; i++) g_cnt[base + i] = 0;
}

// ---------------- CSR fill (info only, R9 scalar form) -----------------------
__global__ __launch_bounds__(256) void k_fill(
    const int* __restrict__ snod, const int* __restrict__ enod)
{
    int t = blockIdx.x * 256 + threadIdx.x;       // 524288
    int jm = (t >> 11) & 7;
    int bh = t >> 14;
    int nidx = t;
    int sv = snod[nidx];
    if (sv < 0) return;
    int ev = enod[nidx] & (Ss - 1);
    int sv2 = sv & (Ss - 1);
    int base = bh * Ss;
    int cbase = bh * (TR * Ss);
    if (jm != 0) {
        int pos = g_off[bh * (Ss + 1) + ev] + atomicAdd(&g_cnt[base + ev], 1);
        g_info[cbase + pos] = sv2 | (jm << 12);            // q=ev, k=sv, j=jm
    }
    {
        int pos = g_off[bh * (Ss + 1) + sv2] + atomicAdd(&g_cnt[base + sv2], 1);
        g_info[cbase + pos] = ev | ((jm + 8) << 12);       // q=sv, k=ev, j=jm+8
    }
}

// --------- per-node: score + softmax + weighted sum in ONE pass --------------
// warp per node; lane covers dims 2*lane, 2*lane+1. Single uint2 gather per
// entry (interleaved fp16 kv); next entry's info+kv prefetched during reduce.
__global__ __launch_bounds__(256) void k_aggr(
    const float* __restrict__ rq, const float* __restrict__ rk,
    const float* __restrict__ rv)
{
    int w = (blockIdx.x * 256 + threadIdx.x) >> 5;
    int lane = threadIdx.x & 31;
    int bh = w >> 11;
    int n = w & (Ss - 1);
    int h = bh & (Hh - 1), b = bh >> 3;
    int obase = bh * (Ss + 1) + n;
    int beg = g_off[obase], end = g_off[obase + 1];
    size_t qb = (size_t)(bh * Ss + n) * DK;
    float2 qv = *(const float2*)&g_q[qb + 2 * lane];
    float a0 = 0.f, a1 = 0.f, ds = 0.f;
    int cbase = bh * (TR * Ss);
    const size_t kvrow = (size_t)bh * Ss * 128;

    int info = (beg < end) ? g_info[cbase + beg] : 0;
    uint2 kv = (beg < end)
        ? *(const uint2*)&g_kv[kvrow + (size_t)(info & (Ss - 1)) * 128 + 4 * lane]
        : make_uint2(0, 0);

    for (int i = beg; i < end; i++) {
        const int j = info >> 12;
        const uint2 kvc = kv;
        if (i + 1 < end) {
            info = g_info[cbase + i + 1];
            kv = *(const uint2*)&g_kv[kvrow + (size_t)(info & (Ss - 1)) * 128 + 4 * lane];
        }
        const int rb = (h * TR + j) * DK + 2 * lane;
        float2 kf = __half22float2(*(const __half2*)&kvc.x);
        float2 vf = __half22float2(*(const __half2*)&kvc.y);
        float2 rkv = *(const float2*)&rk[rb];
        float2 rqv = *(const float2*)&rq[rb];
        float p = qv.x * (kf.x + rkv.x) + rqv.x * kf.x
                + qv.y * (kf.y + rkv.y) + rqv.y * kf.y;
#pragma unroll
        for (int off = 16; off; off >>= 1)
            p += __shfl_xor_sync(0xffffffffu, p, off);
        float ev;
        if (lane == 0) ev = __expf(p * (1.0f / 24.0f));
        ev = __shfl_sync(0xffffffffu, ev, 0);
        float2 rvv = *(const float2*)&rv[rb];
        a0 += ev * (vf.x + rvv.x);
        a1 += ev * (vf.y + rvv.y);
        ds += ev;
    }
    float inv = ds > 0.f ? 1.f / ds : 0.f;
    size_t ob = (size_t)((b * Ss + n) * Hh + h) * DK;
    *(__half2*)&g_atth[ob + 2 * lane] = __floats2half2_rn(a0 * inv, a1 * inv);
}

// ---------------- launch --------------------------------------------------
#define GEMM_SMEM (4 * STAGE)

extern "C" void kernel_launch(void* const* d_in, const int* in_sizes, int n_in,
                              void* d_out, int out_size)
{
    const float* query = (const float*)d_in[0];
    const float* key   = (const float*)d_in[1];
    const float* value = (const float*)d_in[2];
    const int*   snod  = (const int*)d_in[3];
    const int*   enod  = (const int*)d_in[4];
    const float* rel_q = (const float*)d_in[5];
    const float* rel_k = (const float*)d_in[6];
    const float* rel_v = (const float*)d_in[7];
    const float* Wq = (const float*)d_in[8];
    const float* bq = (const float*)d_in[9];
    const float* Wk = (const float*)d_in[10];
    const float* bk = (const float*)d_in[11];
    const float* Wv = (const float*)d_in[12];
    const float* bv = (const float*)d_in[13];
    const float* Wo = (const float*)d_in[14];
    const float* bo = (const float*)d_in[15];
    float* out = (float*)d_out;

    cudaFuncSetAttribute(gemm_tc, cudaFuncAttributeMaxDynamicSharedMemorySize, GEMM_SMEM);

    dim3 gcw(Dd * Dd / 4 / 256, 4);
    dim3 gci(MROWS * Dd / 4 / 256, 3);
    dim3 gq(Dd / 64, MROWS / 128, 3);
    dim3 go(Dd / 64, MROWS / 128, 1);

    conv_w<<<gcw, 256>>>(Wq, Wk, Wv, Wo);
    conv_in<<<gci, 256>>>(query, key, value);
    gemm_tc<<<gq, 256, GEMM_SMEM>>>(bq, bk, bv, nullptr, 0);
    conv_kv<<<NNODES * 16 / 256, 256>>>();
    k_count<<<(NBH * Rr * Ss) / 256, 256>>>(snod, enod);
    k_scan<<<NBH, 256>>>();
    k_fill<<<(NBH * Rr * Ss) / 256, 256>>>(snod, enod);
    k_aggr<<<NNODES * 32 / 256, 256>>>(rel_q, rel_k, rel_v);
    gemm_tc<<<go, 256, GEMM_SMEM>>>(bo, nullptr, nullptr, out, 1);
}

// round 14
// speedup vs baseline: 1.6113x; 1.6113x over previous
#include <cuda_runtime.h>
#include <cuda_fp16.h>
#include <math.h>

// Problem constants (fixed by the dataset)
#define Bb   4
#define Ss   2048
#define Dd   512
#define Hh   8
#define DK   64
#define Rr   8
#define TR   16
#define NBH  (Bb*Hh)                // 32
#define NNODES (NBH*Ss)             // 65536
#define NEDGE  (NBH*TR*Ss)          // 1048576
#define MROWS (Bb*Ss)               // 8192

// ---------------- scratch (device globals; no allocation allowed) -------------
__device__ float g_q[NBH*Ss*DK];
__device__ float g_k[NBH*Ss*DK];
__device__ float g_v[NBH*Ss*DK];
__device__ int   g_cnt[NNODES];
__device__ int   g_off[NBH*(Ss+1)];
__device__ int   g_info[NEDGE];
__device__ __align__(16) __half g_ah[3*MROWS*Dd];   // fp16 inputs (q,k,v)
__device__ __align__(16) __half g_wh[4*Dd*Dd];      // weight hi
__device__ __align__(16) __half g_wl[4*Dd*Dd];      // weight lo
__device__ __align__(16) __half g_atth[MROWS*Dd];   // attn output fp16

// ======================= helpers =============================================
__device__ __forceinline__ unsigned su32(const void* p){
    unsigned a;
    asm("{ .reg .u64 t; cvta.to.shared.u64 t, %1; cvt.u32.u64 %0, t; }"
        : "=r"(a) : "l"(p));
    return a;
}
__device__ __forceinline__ void cpa16(unsigned dst, const void* src){
    asm volatile("cp.async.cg.shared.global [%0], [%1], 16;"
                 :: "r"(dst), "l"(src));
}
__device__ __forceinline__ void cpa_commit(){
    asm volatile("cp.async.commit_group;");
}
__device__ __forceinline__ void cpa_wait2(){
    asm volatile("cp.async.wait_group 2;");
}
__device__ __forceinline__ void ldmx4(unsigned* r, unsigned addr){
    asm volatile("ldmatrix.sync.aligned.m8n8.x4.shared.b16 {%0,%1,%2,%3}, [%4];"
                 : "=r"(r[0]), "=r"(r[1]), "=r"(r[2]), "=r"(r[3]) : "r"(addr));
}
__device__ __forceinline__ void mma_f16(float* d, const unsigned* a, const unsigned* b){
    asm volatile(
        "mma.sync.aligned.m16n8k16.row.col.f32.f16.f16.f32 "
        "{%0,%1,%2,%3}, {%4,%5,%6,%7}, {%8,%9}, {%0,%1,%2,%3};"
        : "+f"(d[0]), "+f"(d[1]), "+f"(d[2]), "+f"(d[3])
        : "r"(a[0]), "r"(a[1]), "r"(a[2]), "r"(a[3]), "r"(b[0]), "r"(b[1]));
}
// 64-byte rows, 16B-granule XOR swizzle: conflict-free ldmatrix
__device__ __forceinline__ unsigned swz(unsigned row, unsigned kb){
    return row * 64u + ((((kb >> 4) ^ ((row >> 1) & 3u)) << 4) | (kb & 15u));
}

// ---------------- conversion pre-passes --------------------------------------
__global__ __launch_bounds__(256) void conv_w(
    const float* __restrict__ Wq, const float* __restrict__ Wk,
    const float* __restrict__ Wv, const float* __restrict__ Wo)
{
    const int z = blockIdx.y;
    const float* W = (z == 0) ? Wq : (z == 1) ? Wk : (z == 2) ? Wv : Wo;
    const int i = blockIdx.x * 256 + threadIdx.x;
    float4 v = ((const float4*)W)[i];
    __half hx = __float2half(v.x), hy = __float2half(v.y);
    __half hz = __float2half(v.z), hw = __float2half(v.w);
    const size_t o = (size_t)z * (Dd*Dd) + (size_t)i * 4;
    *(__half2*)&g_wh[o]     = __halves2half2(hx, hy);
    *(__half2*)&g_wh[o + 2] = __halves2half2(hz, hw);
    *(__half2*)&g_wl[o]     = __halves2half2(__float2half(v.x - __half2float(hx)),
                                             __float2half(v.y - __half2float(hy)));
    *(__half2*)&g_wl[o + 2] = __halves2half2(__float2half(v.z - __half2float(hz)),
                                             __float2half(v.w - __half2float(hw)));
}

__global__ __launch_bounds__(256) void conv_in(
    const float* __restrict__ q, const float* __restrict__ k,
    const float* __restrict__ v)
{
    const int z = blockIdx.y;
    const float* X = (z == 0) ? q : (z == 1) ? k : v;
    const int i = blockIdx.x * 256 + threadIdx.x;
    if (z == 0 && i < NNODES) g_cnt[i] = 0;
    float4 val = ((const float4*)X)[i];
    const size_t o = (size_t)z * (MROWS*Dd) + (size_t)i * 4;
    *(__half2*)&g_ah[o]     = __floats2half2_rn(val.x, val.y);
    *(__half2*)&g_ah[o + 2] = __floats2half2_rn(val.z, val.w);
}

// ======== fp16 tensor-core GEMM (R9 version, unchanged) ======================
#define STG_BH 8192
#define STG_BL 12288
#define STAGE  16384

__global__ __launch_bounds__(256, 2) void gemm_tc(
    const float* __restrict__ B0, const float* __restrict__ B1,
    const float* __restrict__ B2, float* __restrict__ C_ext, int mode)
{
    extern __shared__ char dsm[];
    const unsigned sb = su32(dsm);

    const int z = blockIdx.z;
    const __half* A;
    const __half* Wh;
    const __half* Wl;
    const float* bias;
    float* dst;
    if (mode == 0) {
        A = g_ah + (size_t)z * (MROWS*Dd);
        Wh = g_wh + (size_t)z * (Dd*Dd);
        Wl = g_wl + (size_t)z * (Dd*Dd);
        bias = (z == 0) ? B0 : (z == 1) ? B1 : B2;
        dst = (z == 0) ? g_q : (z == 1) ? g_k : g_v;
    } else {
        A = g_atth;
        Wh = g_wh + (size_t)3 * (Dd*Dd);
        Wl = g_wl + (size_t)3 * (Dd*Dd);
        bias = B0;
        dst = C_ext;
    }

    const int tid = threadIdx.x;
    const int wid = tid >> 5, lane = tid & 31;
    const int wm = wid & 3, wn = wid >> 2;
    const int m0 = blockIdx.y * 128, n0 = blockIdx.x * 64;

    const int arow = tid >> 1;
    const int ap0 = (2 * tid) & 3;
    const int brow = tid >> 2, bp = tid & 3;
    const __half* Asrc = A + (size_t)(m0 + arow) * Dd + ap0 * 8;
    const __half* Whsrc = Wh + (size_t)(n0 + brow) * Dd + bp * 8;
    const __half* Wlsrc = Wl + (size_t)(n0 + brow) * Dd + bp * 8;
    const unsigned dA0 = swz(arow, ap0 * 16);
    const unsigned dA1 = swz(arow, ap0 * 16 + 16);
    const unsigned dB  = swz(brow, bp * 16);

    float acc[2][4][4];
#pragma unroll
    for (int mt = 0; mt < 2; mt++)
#pragma unroll
        for (int nt = 0; nt < 4; nt++)
#pragma unroll
            for (int i = 0; i < 4; i++) acc[mt][nt][i] = 0.f;

#pragma unroll
    for (int c = 0; c < 3; c++) {
        const unsigned st = sb + c * STAGE;
        cpa16(st + dA0, Asrc + c * 32);
        cpa16(st + dA1, Asrc + c * 32 + 8);
        cpa16(st + STG_BH + dB, Whsrc + c * 32);
        cpa16(st + STG_BL + dB, Wlsrc + c * 32);
        cpa_commit();
    }

    for (int c = 0; c < 16; c++) {
        cpa_wait2();
        __syncthreads();
        if (c + 3 < 16) {
            const unsigned st = sb + ((c + 3) & 3) * STAGE;
            cpa16(st + dA0, Asrc + (c + 3) * 32);
            cpa16(st + dA1, Asrc + (c + 3) * 32 + 8);
            cpa16(st + STG_BH + dB, Whsrc + (c + 3) * 32);
            cpa16(st + STG_BL + dB, Wlsrc + (c + 3) * 32);
        }
        cpa_commit();

        const unsigned st = sb + (c & 3) * STAGE;
#pragma unroll
        for (int ks = 0; ks < 2; ks++) {
            const unsigned kb = ks * 32;
            unsigned ah[2][4], bh[4][2], bl[4][2];
#pragma unroll
            for (int mt = 0; mt < 2; mt++) {
                unsigned r = wm * 32 + mt * 16 + (lane & 15);
                unsigned kbyte = kb + (lane >> 4) * 16;
                ldmx4(ah[mt], st + swz(r, kbyte));
            }
#pragma unroll
            for (int p = 0; p < 2; p++) {
                unsigned r = wn * 32 + p * 16 + (lane & 7) + ((lane >> 4) << 3);
                unsigned kbyte = kb + ((lane >> 3) & 1) * 16;
                unsigned t[4];
                ldmx4(t, st + STG_BH + swz(r, kbyte));
                bh[2*p][0] = t[0]; bh[2*p][1] = t[1];
                bh[2*p+1][0] = t[2]; bh[2*p+1][1] = t[3];
                ldmx4(t, st + STG_BL + swz(r, kbyte));
                bl[2*p][0] = t[0]; bl[2*p][1] = t[1];
                bl[2*p+1][0] = t[2]; bl[2*p+1][1] = t[3];
            }
#pragma unroll
            for (int mt = 0; mt < 2; mt++)
#pragma unroll
                for (int nt = 0; nt < 4; nt++) {
                    mma_f16(acc[mt][nt], ah[mt], bh[nt]);
                    mma_f16(acc[mt][nt], ah[mt], bl[nt]);
                }
        }
        __syncthreads();
    }

#pragma unroll
    for (int nt = 0; nt < 4; nt++) {
        const int ncol = n0 + wn * 32 + nt * 8 + 2 * (lane & 3);
        const float b0 = bias[ncol], b1 = bias[ncol + 1];
#pragma unroll
        for (int mt = 0; mt < 2; mt++) {
            const int r0 = m0 + wm * 32 + mt * 16 + (lane >> 2);
            float2 v0 = make_float2(acc[mt][nt][0] + b0, acc[mt][nt][1] + b1);
            float2 v1 = make_float2(acc[mt][nt][2] + b0, acc[mt][nt][3] + b1);
            if (mode == 1) {
                *(float2*)(dst + (size_t)r0 * Dd + ncol) = v0;
                *(float2*)(dst + (size_t)(r0 + 8) * Dd + ncol) = v1;
            } else {
                const int h = ncol >> 6, d = ncol & 63;
                int b = r0 >> 11, s = r0 & (Ss - 1);
                *(float2*)(dst + (size_t)(((b * Hh + h) * Ss + s)) * DK + d) = v0;
                b = (r0 + 8) >> 11; s = (r0 + 8) & (Ss - 1);
                *(float2*)(dst + (size_t)(((b * Hh + h) * Ss + s)) * DK + d) = v1;
            }
        }
    }
}

// ---------------- per-edge counting (index-only) -----------------------------
__global__ __launch_bounds__(256) void k_count(
    const int* __restrict__ snod, const int* __restrict__ enod)
{
    int t = blockIdx.x * 256 + threadIdx.x;       // 524288
    int jm = (t >> 11) & 7;
    int bh = t >> 14;
    int sv = snod[t];
    if (sv < 0) return;
    int ev = enod[t] & (Ss - 1);
    int sv2 = sv & (Ss - 1);
    int base = bh * Ss;
    if (jm != 0) atomicAdd(&g_cnt[base + ev], 1);
    atomicAdd(&g_cnt[base + sv2], 1);
}

// ---------------- exclusive scan of per-node counts per (b,h) --------------
__global__ __launch_bounds__(256) void k_scan()
{
    __shared__ int partial[256];
    int bh = blockIdx.x;
    int t = threadIdx.x;
    int base = bh * Ss + t * 8;
    int c[8]; int sum = 0;
#pragma unroll
    for (int i = 0; i < 8; i++) { c[i] = g_cnt[base + i]; sum += c[i]; }
    partial[t] = sum;
    __syncthreads();
    for (int off = 1; off < 256; off <<= 1) {
        int v = (t >= off) ? partial[t - off] : 0;
        __syncthreads();
        partial[t] += v;
        __syncthreads();
    }
    int run = partial[t] - sum;
    int obase = bh * (Ss + 1) + t * 8;
#pragma unroll
    for (int i = 0; i < 8; i++) { g_off[obase + i] = run; run += c[i]; }
    if (t == 255) g_off[bh * (Ss + 1) + Ss] = run;
#pragma unroll
    for (int i = 0; i < 8; i++) g_cnt[base + i] = 0;
}

// ---------------- CSR fill (info only) ---------------------------------------
__global__ __launch_bounds__(256) void k_fill(
    const int* __restrict__ snod, const int* __restrict__ enod)
{
    int t = blockIdx.x * 256 + threadIdx.x;       // 524288
    int jm = (t >> 11) & 7;
    int bh = t >> 14;
    int sv = snod[t];
    if (sv < 0) return;
    int ev = enod[t] & (Ss - 1);
    int sv2 = sv & (Ss - 1);
    int base = bh * Ss;
    int cbase = bh * (TR * Ss);
    if (jm != 0) {
        int pos = g_off[bh * (Ss + 1) + ev] + atomicAdd(&g_cnt[base + ev], 1);
        g_info[cbase + pos] = sv2 | (jm << 12);            // q=ev, k=sv, j=jm
    }
    {
        int pos = g_off[bh * (Ss + 1) + sv2] + atomicAdd(&g_cnt[base + sv2], 1);
        g_info[cbase + pos] = ev | ((jm + 8) << 12);       // q=sv, k=ev, j=jm+8
    }
}

// --------- per-node: score + softmax + weighted sum in ONE pass --------------
// warp per node, split into two independent 16-lane halves processing
// alternate CSR entries. Lane covers 4 contiguous dims (float4 loads).
// 4-deep shfl reduce per half; halves merged once after the loop.
__global__ __launch_bounds__(256) void k_aggr(
    const float* __restrict__ rq, const float* __restrict__ rk,
    const float* __restrict__ rv)
{
    int w = (blockIdx.x * 256 + threadIdx.x) >> 5;
    int lane = threadIdx.x & 31;
    const int half = lane >> 4;          // 0 or 1
    const int hl = lane & 15;            // lane within half
    const unsigned hmask = half ? 0xffff0000u : 0x0000ffffu;
    int bh = w >> 11;
    int n = w & (Ss - 1);
    int h = bh & (Hh - 1), b = bh >> 3;
    int obase = bh * (Ss + 1) + n;
    int beg = g_off[obase], end = g_off[obase + 1];
    size_t qb = (size_t)(bh * Ss + n) * DK;
    const float4 qv = *(const float4*)&g_q[qb + 4 * hl];
    float4 a = make_float4(0.f, 0.f, 0.f, 0.f);
    float ds = 0.f;
    int cbase = bh * (TR * Ss);

    for (int i = beg + half; i < end; i += 2) {
        int info = g_info[cbase + i];
        int kn = info & (Ss - 1);
        int j = info >> 12;
        size_t kb = (size_t)(bh * Ss + kn) * DK;
        int rb = (h * TR + j) * DK + 4 * hl;
        float4 kf  = *(const float4*)&g_k[kb + 4 * hl];
        float4 rkv = *(const float4*)&rk[rb];
        float4 rqv = *(const float4*)&rq[rb];
        float p = qv.x * (kf.x + rkv.x) + rqv.x * kf.x
                + qv.y * (kf.y + rkv.y) + rqv.y * kf.y
                + qv.z * (kf.z + rkv.z) + rqv.z * kf.z
                + qv.w * (kf.w + rkv.w) + rqv.w * kf.w;
#pragma unroll
        for (int off = 8; off; off >>= 1)
            p += __shfl_xor_sync(hmask, p, off);
        float ev;
        if (hl == 0) ev = __expf(p * (1.0f / 24.0f));
        ev = __shfl_sync(hmask, ev, half * 16);
        float4 vf  = *(const float4*)&g_v[kb + 4 * hl];
        float4 rvv = *(const float4*)&rv[rb];
        a.x += ev * (vf.x + rvv.x);
        a.y += ev * (vf.y + rvv.y);
        a.z += ev * (vf.z + rvv.z);
        a.w += ev * (vf.w + rvv.w);
        ds += ev;
    }
    // merge the two halves (same dims in both halves)
    a.x += __shfl_xor_sync(0xffffffffu, a.x, 16);
    a.y += __shfl_xor_sync(0xffffffffu, a.y, 16);
    a.z += __shfl_xor_sync(0xffffffffu, a.z, 16);
    a.w += __shfl_xor_sync(0xffffffffu, a.w, 16);
    ds  += __shfl_xor_sync(0xffffffffu, ds, 16);

    if (half == 0) {
        float inv = ds > 0.f ? 1.f / ds : 0.f;
        size_t ob = (size_t)((b * Ss + n) * Hh + h) * DK;
        __half2 o0 = __floats2half2_rn(a.x * inv, a.y * inv);
        __half2 o1 = __floats2half2_rn(a.z * inv, a.w * inv);
        uint2 ov;
        ov.x = *(unsigned*)&o0; ov.y = *(unsigned*)&o1;
        *(uint2*)&g_atth[ob + 4 * hl] = ov;
    }
}

// ---------------- launch --------------------------------------------------
#define GEMM_SMEM (4 * STAGE)

extern "C" void kernel_launch(void* const* d_in, const int* in_sizes, int n_in,
                              void* d_out, int out_size)
{
    const float* query = (const float*)d_in[0];
    const float* key   = (const float*)d_in[1];
    const float* value = (const float*)d_in[2];
    const int*   snod  = (const int*)d_in[3];
    const int*   enod  = (const int*)d_in[4];
    const float* rel_q = (const float*)d_in[5];
    const float* rel_k = (const float*)d_in[6];
    const float* rel_v = (const float*)d_in[7];
    const float* Wq = (const float*)d_in[8];
    const float* bq = (const float*)d_in[9];
    const float* Wk = (const float*)d_in[10];
    const float* bk = (const float*)d_in[11];
    const float* Wv = (const float*)d_in[12];
    const float* bv = (const float*)d_in[13];
    const float* Wo = (const float*)d_in[14];
    const float* bo = (const float*)d_in[15];
    float* out = (float*)d_out;

    cudaFuncSetAttribute(gemm_tc, cudaFuncAttributeMaxDynamicSharedMemorySize, GEMM_SMEM);

    dim3 gcw(Dd * Dd / 4 / 256, 4);
    dim3 gci(MROWS * Dd / 4 / 256, 3);
    dim3 gq(Dd / 64, MROWS / 128, 3);
    dim3 go(Dd / 64, MROWS / 128, 1);

    conv_w<<<gcw, 256>>>(Wq, Wk, Wv, Wo);
    conv_in<<<gci, 256>>>(query, key, value);
    gemm_tc<<<gq, 256, GEMM_SMEM>>>(bq, bk, bv, nullptr, 0);
    k_count<<<(NBH * Rr * Ss) / 256, 256>>>(snod, enod);
    k_scan<<<NBH, 256>>>();
    k_fill<<<(NBH * Rr * Ss) / 256, 256>>>(snod, enod);
    k_aggr<<<NNODES * 32 / 256, 256>>>(rel_q, rel_k, rel_v);
    gemm_tc<<<go, 256, GEMM_SMEM>>>(bo, nullptr, nullptr, out, 1);
}